// round 6
// baseline (speedup 1.0000x reference)
#include <cuda_runtime.h>
#include <cuda_bf16.h>
#include <mma.h>
#include <math.h>
#include <cstdint>

using namespace nvcuda;

#define NN   100000
#define EE   1600000
#define FIN  256
#define FOUT 128
#define SCAN_BLK 1024
#define NBLK ((NN + SCAN_BLK - 1) / SCAN_BLK)   // 98

// Scratch (static __device__)
__device__ float g_y[(size_t)NN * FOUT];
__device__ int   g_degi[NN];
__device__ float g_dinv[NN];
__device__ int   g_start[NN];
__device__ int   g_cursor[NN];
__device__ int   g_srow[EE];
__device__ int   g_bsum[NBLK];
__device__ float g_hsum[FOUT];
__device__ __nv_bfloat16 g_Bhi[FIN * FOUT];          // W split [k][n]
__device__ __nv_bfloat16 g_Blo[FIN * FOUT];
__device__ __nv_bfloat16 g_Ahi[(size_t)NN * FIN];    // A split [row][k]
__device__ __nv_bfloat16 g_Alo[(size_t)NN * FIN];

static __device__ __forceinline__ uint32_t s2u(const void* p) {
    return (uint32_t)__cvta_generic_to_shared(p);
}
static __device__ __forceinline__ void cpasync16(uint32_t dst, const void* src, int src_bytes) {
    asm volatile("cp.async.cg.shared.global [%0], [%1], 16, %2;"
                 :: "r"(dst), "l"(src), "r"(src_bytes) : "memory");
}

// ---------------------------------------------------------------------------
// 1. Fused: zero degree hist + split W + split A (streaming)
__global__ void k_conv(const float* __restrict__ A, const float* __restrict__ W) {
    int i = blockIdx.x * blockDim.x + threadIdx.x;
    int stride = gridDim.x * blockDim.x;
    // zero degi
    for (int j = i; j < NN; j += stride) g_degi[j] = 0;
    // split W: [k][n] fp32 -> bf16 hi/lo
    for (int j = i; j < FIN * FOUT; j += stride) {
        float x = W[j];
        __nv_bfloat16 h = __float2bfloat16(x);
        g_Bhi[j] = h;
        g_Blo[j] = __float2bfloat16(x - __bfloat162float(h));
    }
    // split A: 4 floats per thread-iter
    const int total4 = NN * FIN / 4;
    for (int j = i; j < total4; j += stride) {
        float4 f = ((const float4*)A)[j];
        __nv_bfloat162 h0 = __float22bfloat162_rn(make_float2(f.x, f.y));
        __nv_bfloat162 h1 = __float22bfloat162_rn(make_float2(f.z, f.w));
        float2 hf0 = __bfloat1622float2(h0);
        float2 hf1 = __bfloat1622float2(h1);
        __nv_bfloat162 l0 = __float22bfloat162_rn(make_float2(f.x - hf0.x, f.y - hf0.y));
        __nv_bfloat162 l1 = __float22bfloat162_rn(make_float2(f.z - hf1.x, f.w - hf1.y));
        ((uint2*)g_Ahi)[j] = make_uint2(*(uint32_t*)&h0, *(uint32_t*)&h1);
        ((uint2*)g_Alo)[j] = make_uint2(*(uint32_t*)&l0, *(uint32_t*)&l1);
    }
}

__global__ void k_deg(const int* __restrict__ col, int e) {
    int i = blockIdx.x * blockDim.x + threadIdx.x;
    if (i < e) atomicAdd(&g_degi[col[i]], 1);
}

// scan1 + fused dinv
__global__ void k_scan1() {
    __shared__ int sd[SCAN_BLK];
    int tx = threadIdx.x;
    int i = blockIdx.x * SCAN_BLK + tx;
    int v = (i < NN) ? g_degi[i] : 0;
    if (i < NN) g_dinv[i] = rsqrtf((float)(v + 1));
    sd[tx] = v;
    __syncthreads();
#pragma unroll
    for (int off = 1; off < SCAN_BLK; off <<= 1) {
        int t = (tx >= off) ? sd[tx - off] : 0;
        __syncthreads();
        sd[tx] += t;
        __syncthreads();
    }
    if (i < NN) g_start[i] = sd[tx] - v;
    if (tx == SCAN_BLK - 1) g_bsum[blockIdx.x] = sd[tx];
}
__global__ void k_scan2() {
    int tx = threadIdx.x;
    if (tx < FOUT) g_hsum[tx] = 0.0f;
    if (tx == 0) {
        int acc = 0;
        for (int b = 0; b < NBLK; b++) { int t = g_bsum[b]; g_bsum[b] = acc; acc += t; }
    }
}
__global__ void k_scan3() {
    int i = blockIdx.x * SCAN_BLK + threadIdx.x;
    if (i < NN) {
        int s = g_start[i] + g_bsum[blockIdx.x];
        g_start[i]  = s;
        g_cursor[i] = s;
    }
}
__global__ void k_sort(const int* __restrict__ row, const int* __restrict__ col, int e) {
    int i = blockIdx.x * blockDim.x + threadIdx.x;
    if (i < e) {
        int p = atomicAdd(&g_cursor[col[i]], 1);
        g_srow[p] = row[i];
    }
}

// ---------------------------------------------------------------------------
// bf16x3 GEMM, cp.async pipelined. CTA tile 128x128, 8 warps (4x2), warp 32x64.
// All of B (256k x 128n, hi+lo) preloaded; A chunk (128r x 64k) double-buffered.
#define A_LD   72     // bf16 elems per A smem row (144 B)
#define B_LD   136
#define A_BUF_BYTES (128 * A_LD * 2)        // 18432 per tensor
#define AH0 0
#define AL0 (AH0 + A_BUF_BYTES)
#define AH1 (AL0 + A_BUF_BYTES)
#define AL1 (AH1 + A_BUF_BYTES)
#define BH_OFF (AL1 + A_BUF_BYTES)          // 73728
#define BL_OFF (BH_OFF + FIN * B_LD * 2)    // +69632
#define GEMM_SMEM (BL_OFF + FIN * B_LD * 2) // 212992

__global__ void __launch_bounds__(256, 1)
k_gemm_mma(int N) {
    extern __shared__ char sm[];
    const int tx = threadIdx.x;
    const int wid = tx >> 5;
    const int lane = tx & 31;
    const int wr = wid >> 1;
    const int wc = wid & 1;
    const int block_row = blockIdx.x * 128;

    __nv_bfloat16* Bs_h = (__nv_bfloat16*)(sm + BH_OFF);
    __nv_bfloat16* Bs_l = (__nv_bfloat16*)(sm + BL_OFF);

    // --- preload all of B (hi+lo): 256 rows x 128 n, 16 chunks of 16B per row
    {
        uint32_t bh = s2u(sm + BH_OFF), bl = s2u(sm + BL_OFF);
#pragma unroll
        for (int it = 0; it < 16; it++) {
            int t = tx + 256 * it;          // 0..4095
            int k = t >> 4, c16 = t & 15;
            cpasync16(bh + (k * B_LD + c16 * 8) * 2, g_Bhi + k * FOUT + c16 * 8, 16);
            cpasync16(bl + (k * B_LD + c16 * 8) * 2, g_Blo + k * FOUT + c16 * 8, 16);
        }
    }
    // --- prefetch A chunk 0 into buf 0
    {
        uint32_t ah = s2u(sm + AH0), al = s2u(sm + AL0);
#pragma unroll
        for (int it = 0; it < 4; it++) {
            int t = tx + 256 * it;          // 0..1023
            int r = t >> 3, c8 = t & 7;
            int gr = block_row + r;
            int sz = (gr < N) ? 16 : 0;
            const __nv_bfloat16* srch = g_Ahi + (size_t)gr * FIN + c8 * 8;
            const __nv_bfloat16* srcl = g_Alo + (size_t)gr * FIN + c8 * 8;
            cpasync16(ah + (r * A_LD + c8 * 8) * 2, srch, sz);
            cpasync16(al + (r * A_LD + c8 * 8) * 2, srcl, sz);
        }
    }
    asm volatile("cp.async.commit_group;" ::: "memory");

    wmma::fragment<wmma::accumulator, 16, 16, 16, float> acc[2][4];
#pragma unroll
    for (int i = 0; i < 2; i++)
#pragma unroll
        for (int j = 0; j < 4; j++) wmma::fill_fragment(acc[i][j], 0.0f);

    for (int kc = 0; kc < 4; kc++) {
        asm volatile("cp.async.wait_group 0;" ::: "memory");
        __syncthreads();

        // prefetch next A chunk into alternate buffer
        if (kc < 3) {
            int nb = (kc + 1) & 1;
            uint32_t ah = s2u(sm + (nb ? AH1 : AH0)), al = s2u(sm + (nb ? AL1 : AL0));
#pragma unroll
            for (int it = 0; it < 4; it++) {
                int t = tx + 256 * it;
                int r = t >> 3, c8 = t & 7;
                int gr = block_row + r;
                int sz = (gr < N) ? 16 : 0;
                const __nv_bfloat16* srch = g_Ahi + (size_t)gr * FIN + (kc + 1) * 64 + c8 * 8;
                const __nv_bfloat16* srcl = g_Alo + (size_t)gr * FIN + (kc + 1) * 64 + c8 * 8;
                cpasync16(ah + (r * A_LD + c8 * 8) * 2, srch, sz);
                cpasync16(al + (r * A_LD + c8 * 8) * 2, srcl, sz);
            }
            asm volatile("cp.async.commit_group;" ::: "memory");
        }

        const int cb = kc & 1;
        __nv_bfloat16* As_h = (__nv_bfloat16*)(sm + (cb ? AH1 : AH0));
        __nv_bfloat16* As_l = (__nv_bfloat16*)(sm + (cb ? AL1 : AL0));

#pragma unroll
        for (int kk = 0; kk < 4; kk++) {
            wmma::fragment<wmma::matrix_a, 16, 16, 16, __nv_bfloat16, wmma::row_major> ah[2], al[2];
#pragma unroll
            for (int i = 0; i < 2; i++) {
                const __nv_bfloat16* ap = As_h + (wr * 32 + i * 16) * A_LD + kk * 16;
                const __nv_bfloat16* alp = As_l + (wr * 32 + i * 16) * A_LD + kk * 16;
                wmma::load_matrix_sync(ah[i], ap, A_LD);
                wmma::load_matrix_sync(al[i], alp, A_LD);
            }
#pragma unroll
            for (int j = 0; j < 4; j++) {
                wmma::fragment<wmma::matrix_b, 16, 16, 16, __nv_bfloat16, wmma::row_major> bh, bl;
                const __nv_bfloat16* bp  = Bs_h + (kc * 64 + kk * 16) * B_LD + wc * 64 + j * 16;
                const __nv_bfloat16* blp = Bs_l + (kc * 64 + kk * 16) * B_LD + wc * 64 + j * 16;
                wmma::load_matrix_sync(bh, bp, B_LD);
                wmma::load_matrix_sync(bl, blp, B_LD);
#pragma unroll
                for (int i = 0; i < 2; i++) {
                    wmma::mma_sync(acc[i][j], ah[i], bh, acc[i][j]);
                    wmma::mma_sync(acc[i][j], ah[i], bl, acc[i][j]);
                    wmma::mma_sync(acc[i][j], al[i], bh, acc[i][j]);
                }
            }
        }
        __syncthreads();
    }

    // Epilogue: per-warp staging (stride 68 -> conflict-free), scale by dinv
    float* stage = (float*)sm + wid * 2176;
#pragma unroll
    for (int i = 0; i < 2; i++)
#pragma unroll
        for (int j = 0; j < 4; j++)
            wmma::store_matrix_sync(stage + i * 16 * 68 + j * 16, acc[i][j], 68, wmma::mem_row_major);
    __syncwarp();

    int grow = block_row + wr * 32 + lane;
    if (grow < N) {
        float dv = g_dinv[grow];
        float* yp = g_y + (size_t)grow * FOUT + wc * 64;
        const float* sp = stage + lane * 68;
#pragma unroll
        for (int q = 0; q < 16; q++) {
            float4 v = *(const float4*)(sp + q * 4);
            v.x *= dv; v.y *= dv; v.z *= dv; v.w *= dv;
            *(float4*)(yp + q * 4) = v;
        }
    }
}

// ---------------------------------------------------------------------------
// Gather-aggregate + fused epilogue. One warp per destination node.
__global__ void __launch_bounds__(256)
k_agg(const float* __restrict__ b, float* __restrict__ out, int N, int E) {
    __shared__ float hpart[FOUT];
    const int tx = threadIdx.x;
    if (tx < FOUT) hpart[tx] = 0.0f;
    __syncthreads();

    const int lane = tx & 31;
    const int warp = tx >> 5;
    const int node = blockIdx.x * 8 + warp;

    float4 v = make_float4(0.f, 0.f, 0.f, 0.f);
    if (node < N) {
        float4 acc = ((const float4*)(g_y + (size_t)node * FOUT))[lane];
        int s  = g_start[node];
        int e2 = (node + 1 < N) ? g_start[node + 1] : E;

        for (int base = s; base < e2; base += 32) {
            int cnt = min(32, e2 - base);
            int myidx = (lane < cnt) ? g_srow[base + lane] : 0;
            int j = 0;
            for (; j + 4 <= cnt; j += 4) {
                int r0 = __shfl_sync(0xffffffffu, myidx, j + 0);
                int r1 = __shfl_sync(0xffffffffu, myidx, j + 1);
                int r2 = __shfl_sync(0xffffffffu, myidx, j + 2);
                int r3 = __shfl_sync(0xffffffffu, myidx, j + 3);
                float4 v0 = ((const float4*)(g_y + (size_t)r0 * FOUT))[lane];
                float4 v1 = ((const float4*)(g_y + (size_t)r1 * FOUT))[lane];
                float4 v2 = ((const float4*)(g_y + (size_t)r2 * FOUT))[lane];
                float4 v3 = ((const float4*)(g_y + (size_t)r3 * FOUT))[lane];
                acc.x += v0.x + v1.x + v2.x + v3.x;
                acc.y += v0.y + v1.y + v2.y + v3.y;
                acc.z += v0.z + v1.z + v2.z + v3.z;
                acc.w += v0.w + v1.w + v2.w + v3.w;
            }
            for (; j < cnt; j++) {
                int r = __shfl_sync(0xffffffffu, myidx, j);
                float4 vv = ((const float4*)(g_y + (size_t)r * FOUT))[lane];
                acc.x += vv.x; acc.y += vv.y; acc.z += vv.z; acc.w += vv.w;
            }
        }

        float dv = g_dinv[node];
        float4 bv = ((const float4*)b)[lane];
        v.x = fmaxf(fmaf(acc.x, dv, bv.x), 0.0f);
        v.y = fmaxf(fmaf(acc.y, dv, bv.y), 0.0f);
        v.z = fmaxf(fmaf(acc.z, dv, bv.z), 0.0f);
        v.w = fmaxf(fmaf(acc.w, dv, bv.w), 0.0f);
        ((float4*)(out + (size_t)node * FOUT))[lane] = v;
    }

    atomicAdd(&hpart[lane * 4 + 0], v.x);
    atomicAdd(&hpart[lane * 4 + 1], v.y);
    atomicAdd(&hpart[lane * 4 + 2], v.z);
    atomicAdd(&hpart[lane * 4 + 3], v.w);
    __syncthreads();
    if (tx < FOUT) atomicAdd(&g_hsum[tx], hpart[tx]);
}

__global__ void k_h(float* __restrict__ hout, float ninv) {
    int j = threadIdx.x;
    float m = g_hsum[j] * ninv;
    hout[j] = 1.0f / (1.0f + expf(-m));
}

// ---------------------------------------------------------------------------
extern "C" void kernel_launch(void* const* d_in, const int* in_sizes, int n_in,
                              void* d_out, int out_size) {
    const float* feat = (const float*)d_in[0];
    const int*   ei   = (const int*)d_in[1];
    const float* W    = (const float*)d_in[2];
    const float* b    = (const float*)d_in[3];
    float* out = (float*)d_out;

    int N = in_sizes[0] / FIN;
    int E = in_sizes[1] / 2;
    const int* rowp = ei;
    const int* colp = ei + E;

    cudaFuncSetAttribute(k_gemm_mma, cudaFuncAttributeMaxDynamicSharedMemorySize, GEMM_SMEM);

    k_conv<<<1184, 256>>>(feat, W);                 // 8 waves of 148
    k_deg<<<(E + 255) / 256, 256>>>(colp, E);
    k_scan1<<<NBLK, SCAN_BLK>>>();
    k_scan2<<<1, 128>>>();
    k_scan3<<<NBLK, SCAN_BLK>>>();
    k_sort<<<(E + 255) / 256, 256>>>(rowp, colp, E);
    k_gemm_mma<<<(N + 127) / 128, 256, GEMM_SMEM>>>(N);
    k_agg<<<(N + 7) / 8, 256>>>(b, out, N, E);
    k_h<<<1, FOUT>>>(out + (size_t)N * FOUT, 1.0f / (float)N);
}

// round 7
// speedup vs baseline: 1.2323x; 1.2323x over previous
#include <cuda_runtime.h>
#include <cuda_bf16.h>
#include <cuda_fp16.h>
#include <mma.h>
#include <math.h>
#include <cstdint>

using namespace nvcuda;

#define NN   100000
#define EE   1600000
#define FIN  256
#define FOUT 128
#define SCAN_BLK 1024
#define NBLK ((NN + SCAN_BLK - 1) / SCAN_BLK)   // 98

// Scratch (static __device__)
__device__ __half g_yh[(size_t)NN * FOUT];    // y = (A@W)*dinv[row], fp16
__device__ int   g_degi[NN];
__device__ float g_dinv[NN];
__device__ int   g_start[NN];
__device__ int   g_cursor[NN];
__device__ int   g_srow[EE];
__device__ int   g_bsum[NBLK];
__device__ float g_hsum[FOUT];
__device__ int   g_ticket;
__device__ __nv_bfloat16 g_Bhi[FIN * FOUT];   // W split [k][n]
__device__ __nv_bfloat16 g_Blo[FIN * FOUT];

// ---------------------------------------------------------------------------
// 1. Fused init: zero degi/hsum/ticket + split W into bf16 hi/lo
__global__ void k_init(const float* __restrict__ W) {
    int i = blockIdx.x * blockDim.x + threadIdx.x;
    int stride = gridDim.x * blockDim.x;
    for (int j = i; j < NN; j += stride) g_degi[j] = 0;
    for (int j = i; j < FIN * FOUT; j += stride) {
        float x = W[j];
        __nv_bfloat16 h = __float2bfloat16(x);
        g_Bhi[j] = h;
        g_Blo[j] = __float2bfloat16(x - __bfloat162float(h));
    }
    if (i < FOUT) g_hsum[i] = 0.0f;
    if (i == 0)   g_ticket = 0;
}

__global__ void k_deg(const int* __restrict__ col, int e) {
    int i = blockIdx.x * blockDim.x + threadIdx.x;
    if (i < e) atomicAdd(&g_degi[col[i]], 1);
}

// scan1: block-local exclusive scan + fused dinv
__global__ void k_scan1() {
    __shared__ int sd[SCAN_BLK];
    int tx = threadIdx.x;
    int i = blockIdx.x * SCAN_BLK + tx;
    int v = (i < NN) ? g_degi[i] : 0;
    if (i < NN) g_dinv[i] = rsqrtf((float)(v + 1));
    sd[tx] = v;
    __syncthreads();
#pragma unroll
    for (int off = 1; off < SCAN_BLK; off <<= 1) {
        int t = (tx >= off) ? sd[tx - off] : 0;
        __syncthreads();
        sd[tx] += t;
        __syncthreads();
    }
    if (i < NN) g_start[i] = sd[tx] - v;
    if (tx == SCAN_BLK - 1) g_bsum[blockIdx.x] = sd[tx];
}

// scan3: each block scans the 98 partials in smem, adds its offset, inits cursor
__global__ void k_scan3() {
    __shared__ int sb[128];
    int tx = threadIdx.x;
    if (tx < 128) sb[tx] = (tx < NBLK) ? g_bsum[tx] : 0;
    __syncthreads();
#pragma unroll
    for (int off = 1; off < 128; off <<= 1) {
        int t = 0;
        if (tx < 128 && tx >= off) t = sb[tx - off];
        __syncthreads();
        if (tx < 128) sb[tx] += t;
        __syncthreads();
    }
    int boff = (blockIdx.x == 0) ? 0 : sb[blockIdx.x - 1];
    int i = blockIdx.x * SCAN_BLK + tx;
    if (i < NN) {
        int s = g_start[i] + boff;
        g_start[i]  = s;
        g_cursor[i] = s;
    }
}

__global__ void k_sort(const int* __restrict__ row, const int* __restrict__ col, int e) {
    int i = blockIdx.x * blockDim.x + threadIdx.x;
    if (i < e) {
        int p = atomicAdd(&g_cursor[col[i]], 1);
        g_srow[p] = row[i];
    }
}

// ---------------------------------------------------------------------------
// bf16x3 GEMM via wmma (R5 structure): CTA 128x128, 8 warps (4x2), K chunks of 64.
// Epilogue writes y as fp16 (half2), dinv-scaled.
#define A_LD   80
#define B_LD   136
#define AH_OFF 0
#define AL_OFF 20480
#define BH_OFF (AL_OFF + 20480)
#define BL_OFF (BH_OFF + 17408)
#define GEMM_SMEM (BL_OFF + 17408)   // 75776 B

__global__ void __launch_bounds__(256, 2)
k_gemm_mma(const float* __restrict__ A, int N) {
    extern __shared__ char sm[];
    __nv_bfloat16* As_h = (__nv_bfloat16*)(sm + AH_OFF);
    __nv_bfloat16* As_l = (__nv_bfloat16*)(sm + AL_OFF);
    __nv_bfloat16* Bs_h = (__nv_bfloat16*)(sm + BH_OFF);
    __nv_bfloat16* Bs_l = (__nv_bfloat16*)(sm + BL_OFF);

    const int tx = threadIdx.x;
    const int wid = tx >> 5;
    const int lane = tx & 31;
    const int wr = wid >> 1;
    const int wc = wid & 1;
    const int block_row = blockIdx.x * 128;

    wmma::fragment<wmma::accumulator, 16, 16, 16, float> acc[2][4];
#pragma unroll
    for (int i = 0; i < 2; i++)
#pragma unroll
        for (int j = 0; j < 4; j++) wmma::fill_fragment(acc[i][j], 0.0f);

    for (int kc = 0; kc < 4; kc++) {
#pragma unroll
        for (int it = 0; it < 8; it++) {
            int t = tx + 256 * it;
            int r = t >> 4, cq = t & 15;
            int gr = block_row + r;
            float4 f = make_float4(0.f, 0.f, 0.f, 0.f);
            if (gr < N) f = *(const float4*)(A + (size_t)gr * FIN + kc * 64 + cq * 4);
            __nv_bfloat162 h0 = __float22bfloat162_rn(make_float2(f.x, f.y));
            __nv_bfloat162 h1 = __float22bfloat162_rn(make_float2(f.z, f.w));
            float2 hf0 = __bfloat1622float2(h0);
            float2 hf1 = __bfloat1622float2(h1);
            __nv_bfloat162 l0 = __float22bfloat162_rn(make_float2(f.x - hf0.x, f.y - hf0.y));
            __nv_bfloat162 l1 = __float22bfloat162_rn(make_float2(f.z - hf1.x, f.w - hf1.y));
            *(uint2*)(As_h + r * A_LD + cq * 4) = make_uint2(*(uint32_t*)&h0, *(uint32_t*)&h1);
            *(uint2*)(As_l + r * A_LD + cq * 4) = make_uint2(*(uint32_t*)&l0, *(uint32_t*)&l1);
        }
#pragma unroll
        for (int it = 0; it < 4; it++) {
            int t = tx + 256 * it;
            int k = t >> 4, ng = t & 15;
            uint4 vh = *(const uint4*)(g_Bhi + (size_t)(kc * 64 + k) * FOUT + ng * 8);
            uint4 vl = *(const uint4*)(g_Blo + (size_t)(kc * 64 + k) * FOUT + ng * 8);
            *(uint4*)(Bs_h + k * B_LD + ng * 8) = vh;
            *(uint4*)(Bs_l + k * B_LD + ng * 8) = vl;
        }
        __syncthreads();

#pragma unroll
        for (int kk = 0; kk < 4; kk++) {
            wmma::fragment<wmma::matrix_a, 16, 16, 16, __nv_bfloat16, wmma::row_major> ah[2], al[2];
#pragma unroll
            for (int i = 0; i < 2; i++) {
                const __nv_bfloat16* ap = As_h + (wr * 32 + i * 16) * A_LD + kk * 16;
                wmma::load_matrix_sync(ah[i], ap, A_LD);
                wmma::load_matrix_sync(al[i], ap + (AL_OFF - AH_OFF) / 2, A_LD);
            }
#pragma unroll
            for (int j = 0; j < 4; j++) {
                wmma::fragment<wmma::matrix_b, 16, 16, 16, __nv_bfloat16, wmma::row_major> bh, bl;
                const __nv_bfloat16* bp = Bs_h + (kk * 16) * B_LD + wc * 64 + j * 16;
                wmma::load_matrix_sync(bh, bp, B_LD);
                wmma::load_matrix_sync(bl, bp + (BL_OFF - BH_OFF) / 2, B_LD);
#pragma unroll
                for (int i = 0; i < 2; i++) {
                    wmma::mma_sync(acc[i][j], ah[i], bh, acc[i][j]);
                    wmma::mma_sync(acc[i][j], ah[i], bl, acc[i][j]);
                    wmma::mma_sync(acc[i][j], al[i], bh, acc[i][j]);
                }
            }
        }
        __syncthreads();
    }

    // Epilogue: stage fp32, scale by dinv, convert to half2, store to g_yh
    float* stage = (float*)sm + wid * 2176;
#pragma unroll
    for (int i = 0; i < 2; i++)
#pragma unroll
        for (int j = 0; j < 4; j++)
            wmma::store_matrix_sync(stage + i * 16 * 68 + j * 16, acc[i][j], 68, wmma::mem_row_major);
    __syncwarp();

    int grow = block_row + wr * 32 + lane;
    if (grow < N) {
        float dv = g_dinv[grow];
        __half* yp = g_yh + (size_t)grow * FOUT + wc * 64;
        const float* sp = stage + lane * 68;
#pragma unroll
        for (int q = 0; q < 16; q++) {
            float4 v = *(const float4*)(sp + q * 4);
            __half2 p0 = __float22half2_rn(make_float2(v.x * dv, v.y * dv));
            __half2 p1 = __float22half2_rn(make_float2(v.z * dv, v.w * dv));
            *(uint2*)(yp + q * 4) = make_uint2(*(uint32_t*)&p0, *(uint32_t*)&p1);
        }
    }
}

// ---------------------------------------------------------------------------
// Gather-aggregate (fp16 y) + fused epilogue + last-block h. One warp per node.
static __device__ __forceinline__ float4 ldy4(const __half* base, int lane) {
    uint2 u = ((const uint2*)base)[lane];
    __half2 p0 = *(__half2*)&u.x;
    __half2 p1 = *(__half2*)&u.y;
    float2 f0 = __half22float2(p0);
    float2 f1 = __half22float2(p1);
    return make_float4(f0.x, f0.y, f1.x, f1.y);
}

__global__ void __launch_bounds__(256)
k_agg(const float* __restrict__ b, float* __restrict__ out, int N, int E, float ninv) {
    __shared__ float hpart[FOUT];
    __shared__ int is_last;
    const int tx = threadIdx.x;
    if (tx < FOUT) hpart[tx] = 0.0f;
    __syncthreads();

    const int lane = tx & 31;
    const int warp = tx >> 5;
    const int node = blockIdx.x * 8 + warp;

    float4 v = make_float4(0.f, 0.f, 0.f, 0.f);
    if (node < N) {
        float4 acc = ldy4(g_yh + (size_t)node * FOUT, lane);   // self-loop
        int s  = g_start[node];
        int e2 = (node + 1 < N) ? g_start[node + 1] : E;

        for (int base = s; base < e2; base += 32) {
            int cnt = min(32, e2 - base);
            int myidx = (lane < cnt) ? g_srow[base + lane] : 0;
            int j = 0;
            for (; j + 4 <= cnt; j += 4) {
                int r0 = __shfl_sync(0xffffffffu, myidx, j + 0);
                int r1 = __shfl_sync(0xffffffffu, myidx, j + 1);
                int r2 = __shfl_sync(0xffffffffu, myidx, j + 2);
                int r3 = __shfl_sync(0xffffffffu, myidx, j + 3);
                float4 v0 = ldy4(g_yh + (size_t)r0 * FOUT, lane);
                float4 v1 = ldy4(g_yh + (size_t)r1 * FOUT, lane);
                float4 v2 = ldy4(g_yh + (size_t)r2 * FOUT, lane);
                float4 v3 = ldy4(g_yh + (size_t)r3 * FOUT, lane);
                acc.x += v0.x + v1.x + v2.x + v3.x;
                acc.y += v0.y + v1.y + v2.y + v3.y;
                acc.z += v0.z + v1.z + v2.z + v3.z;
                acc.w += v0.w + v1.w + v2.w + v3.w;
            }
            for (; j < cnt; j++) {
                int r = __shfl_sync(0xffffffffu, myidx, j);
                float4 vv = ldy4(g_yh + (size_t)r * FOUT, lane);
                acc.x += vv.x; acc.y += vv.y; acc.z += vv.z; acc.w += vv.w;
            }
        }

        float dv = g_dinv[node];
        float4 bv = ((const float4*)b)[lane];
        v.x = fmaxf(fmaf(acc.x, dv, bv.x), 0.0f);
        v.y = fmaxf(fmaf(acc.y, dv, bv.y), 0.0f);
        v.z = fmaxf(fmaf(acc.z, dv, bv.z), 0.0f);
        v.w = fmaxf(fmaf(acc.w, dv, bv.w), 0.0f);
        ((float4*)(out + (size_t)node * FOUT))[lane] = v;
    }

    atomicAdd(&hpart[lane * 4 + 0], v.x);
    atomicAdd(&hpart[lane * 4 + 1], v.y);
    atomicAdd(&hpart[lane * 4 + 2], v.z);
    atomicAdd(&hpart[lane * 4 + 3], v.w);
    __syncthreads();
    if (tx < FOUT) atomicAdd(&g_hsum[tx], hpart[tx]);

    // last-block computes h
    if (tx == 0) {
        __threadfence();
        int t = atomicAdd(&g_ticket, 1);
        is_last = (t == (int)gridDim.x - 1) ? 1 : 0;
    }
    __syncthreads();
    if (is_last) {
        __threadfence();
        if (tx < FOUT) {
            float m = g_hsum[tx] * ninv;
            out[(size_t)N * FOUT + tx] = 1.0f / (1.0f + expf(-m));
        }
    }
}

// ---------------------------------------------------------------------------
extern "C" void kernel_launch(void* const* d_in, const int* in_sizes, int n_in,
                              void* d_out, int out_size) {
    const float* feat = (const float*)d_in[0];
    const int*   ei   = (const int*)d_in[1];
    const float* W    = (const float*)d_in[2];
    const float* b    = (const float*)d_in[3];
    float* out = (float*)d_out;

    int N = in_sizes[0] / FIN;
    int E = in_sizes[1] / 2;
    const int* rowp = ei;
    const int* colp = ei + E;

    cudaFuncSetAttribute(k_gemm_mma, cudaFuncAttributeMaxDynamicSharedMemorySize, GEMM_SMEM);

    k_init<<<392, 256>>>(W);
    k_deg<<<(E + 255) / 256, 256>>>(colp, E);
    k_scan1<<<NBLK, SCAN_BLK>>>();
    k_scan3<<<NBLK, SCAN_BLK>>>();
    k_sort<<<(E + 255) / 256, 256>>>(rowp, colp, E);
    k_gemm_mma<<<(N + 127) / 128, 256, GEMM_SMEM>>>(feat, N);
    k_agg<<<(N + 7) / 8, 256>>>(b, out, N, E, 1.0f / (float)N);
}

// round 8
// speedup vs baseline: 1.2444x; 1.0098x over previous
#include <cuda_runtime.h>
#include <cuda_bf16.h>
#include <cuda_fp16.h>
#include <mma.h>
#include <math.h>
#include <cstdint>

using namespace nvcuda;

#define NN   100000
#define EE   1600000
#define FIN  256
#define FOUT 128
#define SCAN_BLK 1024
#define NBLK ((NN + SCAN_BLK - 1) / SCAN_BLK)   // 98

// Scratch (static __device__)
__device__ __half g_yh[(size_t)NN * FOUT];    // y = (A@W)*dinv[row], fp16
__device__ int   g_degi[NN];
__device__ float g_dinv[NN];
__device__ int   g_start[NN];
__device__ int   g_cursor[NN];
__device__ int   g_srow[EE];
__device__ int   g_bsum[NBLK];
__device__ float g_hsum[FOUT];
__device__ int   g_ticket;
__device__ __nv_bfloat16 g_Bhi[FIN * FOUT];   // W split [k][n]
__device__ __nv_bfloat16 g_Blo[FIN * FOUT];

static __device__ __forceinline__ uint32_t s2u(const void* p) {
    return (uint32_t)__cvta_generic_to_shared(p);
}
static __device__ __forceinline__ void cpasync16(uint32_t dst, const void* src) {
    asm volatile("cp.async.cg.shared.global [%0], [%1], 16;"
                 :: "r"(dst), "l"(src) : "memory");
}

// ---------------------------------------------------------------------------
// 1. Fused init: zero degi/hsum/ticket + split W into bf16 hi/lo
__global__ void k_init(const float* __restrict__ W) {
    int i = blockIdx.x * blockDim.x + threadIdx.x;
    int stride = gridDim.x * blockDim.x;
    for (int j = i; j < NN; j += stride) g_degi[j] = 0;
    for (int j = i; j < FIN * FOUT; j += stride) {
        float x = W[j];
        __nv_bfloat16 h = __float2bfloat16(x);
        g_Bhi[j] = h;
        g_Blo[j] = __float2bfloat16(x - __bfloat162float(h));
    }
    if (i < FOUT) g_hsum[i] = 0.0f;
    if (i == 0)   g_ticket = 0;
}

__global__ void k_deg(const int* __restrict__ col, int e) {
    int i = blockIdx.x * blockDim.x + threadIdx.x;
    if (i < e) atomicAdd(&g_degi[col[i]], 1);
}

// scan1: block-local exclusive scan + fused dinv
__global__ void k_scan1() {
    __shared__ int sd[SCAN_BLK];
    int tx = threadIdx.x;
    int i = blockIdx.x * SCAN_BLK + tx;
    int v = (i < NN) ? g_degi[i] : 0;
    if (i < NN) g_dinv[i] = rsqrtf((float)(v + 1));
    sd[tx] = v;
    __syncthreads();
#pragma unroll
    for (int off = 1; off < SCAN_BLK; off <<= 1) {
        int t = (tx >= off) ? sd[tx - off] : 0;
        __syncthreads();
        sd[tx] += t;
        __syncthreads();
    }
    if (i < NN) g_start[i] = sd[tx] - v;
    if (tx == SCAN_BLK - 1) g_bsum[blockIdx.x] = sd[tx];
}

// scan3: each block scans the 98 partials in smem, adds offset, inits cursor
__global__ void k_scan3() {
    __shared__ int sb[128];
    int tx = threadIdx.x;
    if (tx < 128) sb[tx] = (tx < NBLK) ? g_bsum[tx] : 0;
    __syncthreads();
#pragma unroll
    for (int off = 1; off < 128; off <<= 1) {
        int t = 0;
        if (tx < 128 && tx >= off) t = sb[tx - off];
        __syncthreads();
        if (tx < 128) sb[tx] += t;
        __syncthreads();
    }
    int boff = (blockIdx.x == 0) ? 0 : sb[blockIdx.x - 1];
    int i = blockIdx.x * SCAN_BLK + tx;
    if (i < NN) {
        int s = g_start[i] + boff;
        g_start[i]  = s;
        g_cursor[i] = s;
    }
}

__global__ void k_sort(const int* __restrict__ row, const int* __restrict__ col, int e) {
    int i = blockIdx.x * blockDim.x + threadIdx.x;
    if (i < e) {
        int p = atomicAdd(&g_cursor[col[i]], 1);
        g_srow[p] = row[i];
    }
}

// ---------------------------------------------------------------------------
// bf16x3 GEMM via wmma. CTA 128x128, 8 warps (4x2), K chunks of 64.
// A_LD=72 (144B stride: 16*r mod 128 covers all 8 phases -> LDSM conflict-free).
#define A_LD   72
#define B_LD   136
#define AH_OFF 0
#define AL_OFF (128 * A_LD * 2)              // 18432
#define BH_OFF (AL_OFF + 128 * A_LD * 2)     // 36864
#define BL_OFF (BH_OFF + 64 * B_LD * 2)      // +17408
#define GEMM_SMEM (BL_OFF + 64 * B_LD * 2)   // 71680

__global__ void __launch_bounds__(256, 2)
k_gemm_mma(const float* __restrict__ A, int N) {
    extern __shared__ char sm[];
    __nv_bfloat16* As_h = (__nv_bfloat16*)(sm + AH_OFF);
    __nv_bfloat16* As_l = (__nv_bfloat16*)(sm + AL_OFF);
    __nv_bfloat16* Bs_h = (__nv_bfloat16*)(sm + BH_OFF);
    __nv_bfloat16* Bs_l = (__nv_bfloat16*)(sm + BL_OFF);

    const int tx = threadIdx.x;
    const int wid = tx >> 5;
    const int lane = tx & 31;
    const int wr = wid >> 1;
    const int wc = wid & 1;
    const int block_row = blockIdx.x * 128;

    wmma::fragment<wmma::accumulator, 16, 16, 16, float> acc[2][4];
#pragma unroll
    for (int i = 0; i < 2; i++)
#pragma unroll
        for (int j = 0; j < 4; j++) wmma::fill_fragment(acc[i][j], 0.0f);

    for (int kc = 0; kc < 4; kc++) {
        // B chunk via cp.async (64 k-rows x 128 n, hi+lo)
        {
            uint32_t bh = s2u(Bs_h), bl = s2u(Bs_l);
#pragma unroll
            for (int it = 0; it < 4; it++) {
                int t = tx + 256 * it;
                int k = t >> 4, ng = t & 15;
                cpasync16(bh + (k * B_LD + ng * 8) * 2, g_Bhi + (size_t)(kc * 64 + k) * FOUT + ng * 8);
                cpasync16(bl + (k * B_LD + ng * 8) * 2, g_Blo + (size_t)(kc * 64 + k) * FOUT + ng * 8);
            }
            asm volatile("cp.async.commit_group;" ::: "memory");
        }
        // A chunk: 128 rows x 64 k fp32 -> bf16 hi/lo
#pragma unroll
        for (int it = 0; it < 8; it++) {
            int t = tx + 256 * it;
            int r = t >> 4, cq = t & 15;
            int gr = block_row + r;
            float4 f = make_float4(0.f, 0.f, 0.f, 0.f);
            if (gr < N) f = *(const float4*)(A + (size_t)gr * FIN + kc * 64 + cq * 4);
            __nv_bfloat162 h0 = __float22bfloat162_rn(make_float2(f.x, f.y));
            __nv_bfloat162 h1 = __float22bfloat162_rn(make_float2(f.z, f.w));
            float2 hf0 = __bfloat1622float2(h0);
            float2 hf1 = __bfloat1622float2(h1);
            __nv_bfloat162 l0 = __float22bfloat162_rn(make_float2(f.x - hf0.x, f.y - hf0.y));
            __nv_bfloat162 l1 = __float22bfloat162_rn(make_float2(f.z - hf1.x, f.w - hf1.y));
            *(uint2*)(As_h + r * A_LD + cq * 4) = make_uint2(*(uint32_t*)&h0, *(uint32_t*)&h1);
            *(uint2*)(As_l + r * A_LD + cq * 4) = make_uint2(*(uint32_t*)&l0, *(uint32_t*)&l1);
        }
        asm volatile("cp.async.wait_group 0;" ::: "memory");
        __syncthreads();

#pragma unroll
        for (int kk = 0; kk < 4; kk++) {
            wmma::fragment<wmma::matrix_a, 16, 16, 16, __nv_bfloat16, wmma::row_major> ah[2], al[2];
#pragma unroll
            for (int i = 0; i < 2; i++) {
                const __nv_bfloat16* ap = As_h + (wr * 32 + i * 16) * A_LD + kk * 16;
                wmma::load_matrix_sync(ah[i], ap, A_LD);
                wmma::load_matrix_sync(al[i], ap + (AL_OFF - AH_OFF) / 2, A_LD);
            }
#pragma unroll
            for (int j = 0; j < 4; j++) {
                wmma::fragment<wmma::matrix_b, 16, 16, 16, __nv_bfloat16, wmma::row_major> bh, bl;
                const __nv_bfloat16* bp = Bs_h + (kk * 16) * B_LD + wc * 64 + j * 16;
                wmma::load_matrix_sync(bh, bp, B_LD);
                wmma::load_matrix_sync(bl, bp + (BL_OFF - BH_OFF) / 2, B_LD);
#pragma unroll
                for (int i = 0; i < 2; i++) {
                    wmma::mma_sync(acc[i][j], ah[i], bh, acc[i][j]);
                    wmma::mma_sync(acc[i][j], ah[i], bl, acc[i][j]);
                    wmma::mma_sync(acc[i][j], al[i], bh, acc[i][j]);
                }
            }
        }
        __syncthreads();
    }

    // Epilogue: stage fp32 (stride 68 -> conflict-free), scale by dinv, fp16 out
    float* stage = (float*)sm + wid * 2176;
#pragma unroll
    for (int i = 0; i < 2; i++)
#pragma unroll
        for (int j = 0; j < 4; j++)
            wmma::store_matrix_sync(stage + i * 16 * 68 + j * 16, acc[i][j], 68, wmma::mem_row_major);
    __syncwarp();

    int grow = block_row + wr * 32 + lane;
    if (grow < N) {
        float dv = g_dinv[grow];
        __half* yp = g_yh + (size_t)grow * FOUT + wc * 64;
        const float* sp = stage + lane * 68;
#pragma unroll
        for (int q = 0; q < 16; q++) {
            float4 v = *(const float4*)(sp + q * 4);
            __half2 p0 = __float22half2_rn(make_float2(v.x * dv, v.y * dv));
            __half2 p1 = __float22half2_rn(make_float2(v.z * dv, v.w * dv));
            *(uint2*)(yp + q * 4) = make_uint2(*(uint32_t*)&p0, *(uint32_t*)&p1);
        }
    }
}

// ---------------------------------------------------------------------------
// Gather-aggregate (fp16 y) + fused epilogue + last-block h. One warp per node.
static __device__ __forceinline__ float4 ldy4(const __half* base, int lane) {
    uint2 u = ((const uint2*)base)[lane];
    __half2 p0 = *(__half2*)&u.x;
    __half2 p1 = *(__half2*)&u.y;
    float2 f0 = __half22float2(p0);
    float2 f1 = __half22float2(p1);
    return make_float4(f0.x, f0.y, f1.x, f1.y);
}

__global__ void __launch_bounds__(256)
k_agg(const float* __restrict__ b, float* __restrict__ out, int N, int E, float ninv) {
    __shared__ float hpart[FOUT];
    __shared__ int is_last;
    const int tx = threadIdx.x;
    if (tx < FOUT) hpart[tx] = 0.0f;
    __syncthreads();

    const int lane = tx & 31;
    const int warp = tx >> 5;
    const int node = blockIdx.x * 8 + warp;

    float4 v = make_float4(0.f, 0.f, 0.f, 0.f);
    if (node < N) {
        float4 acc = ldy4(g_yh + (size_t)node * FOUT, lane);   // self-loop
        int s  = g_start[node];
        int e2 = (node + 1 < N) ? g_start[node + 1] : E;

        for (int base = s; base < e2; base += 32) {
            int cnt = min(32, e2 - base);
            int myidx = (lane < cnt) ? g_srow[base + lane] : 0;
            int j = 0;
            for (; j + 4 <= cnt; j += 4) {
                int r0 = __shfl_sync(0xffffffffu, myidx, j + 0);
                int r1 = __shfl_sync(0xffffffffu, myidx, j + 1);
                int r2 = __shfl_sync(0xffffffffu, myidx, j + 2);
                int r3 = __shfl_sync(0xffffffffu, myidx, j + 3);
                float4 v0 = ldy4(g_yh + (size_t)r0 * FOUT, lane);
                float4 v1 = ldy4(g_yh + (size_t)r1 * FOUT, lane);
                float4 v2 = ldy4(g_yh + (size_t)r2 * FOUT, lane);
                float4 v3 = ldy4(g_yh + (size_t)r3 * FOUT, lane);
                acc.x += v0.x + v1.x + v2.x + v3.x;
                acc.y += v0.y + v1.y + v2.y + v3.y;
                acc.z += v0.z + v1.z + v2.z + v3.z;
                acc.w += v0.w + v1.w + v2.w + v3.w;
            }
            for (; j < cnt; j++) {
                int r = __shfl_sync(0xffffffffu, myidx, j);
                float4 vv = ldy4(g_yh + (size_t)r * FOUT, lane);
                acc.x += vv.x; acc.y += vv.y; acc.z += vv.z; acc.w += vv.w;
            }
        }

        float dv = g_dinv[node];
        float4 bv = ((const float4*)b)[lane];
        v.x = fmaxf(fmaf(acc.x, dv, bv.x), 0.0f);
        v.y = fmaxf(fmaf(acc.y, dv, bv.y), 0.0f);
        v.z = fmaxf(fmaf(acc.z, dv, bv.z), 0.0f);
        v.w = fmaxf(fmaf(acc.w, dv, bv.w), 0.0f);
        ((float4*)(out + (size_t)node * FOUT))[lane] = v;
    }

    atomicAdd(&hpart[lane * 4 + 0], v.x);
    atomicAdd(&hpart[lane * 4 + 1], v.y);
    atomicAdd(&hpart[lane * 4 + 2], v.z);
    atomicAdd(&hpart[lane * 4 + 3], v.w);
    __syncthreads();
    if (tx < FOUT) atomicAdd(&g_hsum[tx], hpart[tx]);

    if (tx == 0) {
        __threadfence();
        int t = atomicAdd(&g_ticket, 1);
        is_last = (t == (int)gridDim.x - 1) ? 1 : 0;
    }
    __syncthreads();
    if (is_last) {
        __threadfence();
        if (tx < FOUT) {
            float m = g_hsum[tx] * ninv;
            out[(size_t)N * FOUT + tx] = 1.0f / (1.0f + expf(-m));
        }
    }
}

// ---------------------------------------------------------------------------
extern "C" void kernel_launch(void* const* d_in, const int* in_sizes, int n_in,
                              void* d_out, int out_size) {
    const float* feat = (const float*)d_in[0];
    const int*   ei   = (const int*)d_in[1];
    const float* W    = (const float*)d_in[2];
    const float* b    = (const float*)d_in[3];
    float* out = (float*)d_out;

    int N = in_sizes[0] / FIN;
    int E = in_sizes[1] / 2;
    const int* rowp = ei;
    const int* colp = ei + E;

    cudaFuncSetAttribute(k_gemm_mma, cudaFuncAttributeMaxDynamicSharedMemorySize, GEMM_SMEM);

    // Launch order puts the GEMM at index 3 (the slot ncu captures).
    k_init<<<392, 256>>>(W);                         // 0
    k_deg<<<(E + 255) / 256, 256>>>(colp, E);        // 1
    k_scan1<<<NBLK, SCAN_BLK>>>();                   // 2  (produces dinv)
    k_gemm_mma<<<(N + 127) / 128, 256, GEMM_SMEM>>>(feat, N);  // 3  <- profiled
    k_scan3<<<NBLK, SCAN_BLK>>>();                   // 4
    k_sort<<<(E + 255) / 256, 256>>>(rowp, colp, E); // 5
    k_agg<<<(N + 7) / 8, 256>>>(b, out, N, E, 1.0f / (float)N);  // 6
}

// round 9
// speedup vs baseline: 1.3537x; 1.0878x over previous
#include <cuda_runtime.h>
#include <cuda_bf16.h>
#include <cuda_fp16.h>
#include <mma.h>
#include <math.h>
#include <cstdint>

using namespace nvcuda;

#define NN   100000
#define EE   1600000
#define FIN  256
#define FOUT 128
#define SCAN_BLK 1024
#define NBLK ((NN + SCAN_BLK - 1) / SCAN_BLK)   // 98

// Scratch (static __device__)
__device__ __half g_yh[(size_t)NN * FOUT];    // y = A@W (UNSCALED), fp16
__device__ int   g_degi[NN];
__device__ float g_dinv[NN];
__device__ int   g_start[NN];
__device__ int   g_cursor[NN];
__device__ int   g_srow[EE];
__device__ int   g_bsum[NBLK];
__device__ float g_hsum[FOUT];
__device__ int   g_ticket;
__device__ __nv_bfloat16 g_Bhi[FIN * FOUT];   // W split [k][n]
__device__ __nv_bfloat16 g_Blo[FIN * FOUT];

static __device__ __forceinline__ uint32_t s2u(const void* p) {
    return (uint32_t)__cvta_generic_to_shared(p);
}
static __device__ __forceinline__ void cpasync16(uint32_t dst, const void* src) {
    asm volatile("cp.async.cg.shared.global [%0], [%1], 16;"
                 :: "r"(dst), "l"(src) : "memory");
}

// ---------------------------------------------------------------------------
// main-stream init: zero degi/hsum/ticket
__global__ void k_zero() {
    int i = blockIdx.x * blockDim.x + threadIdx.x;
    int stride = gridDim.x * blockDim.x;
    for (int j = i; j < NN; j += stride) g_degi[j] = 0;
    if (i < FOUT) g_hsum[i] = 0.0f;
    if (i == 0)   g_ticket = 0;
}

// gemm-stream init: split W into bf16 hi/lo
__global__ void k_initW(const float* __restrict__ W) {
    int i = blockIdx.x * blockDim.x + threadIdx.x;
    if (i < FIN * FOUT) {
        float x = W[i];
        __nv_bfloat16 h = __float2bfloat16(x);
        g_Bhi[i] = h;
        g_Blo[i] = __float2bfloat16(x - __bfloat162float(h));
    }
}

__global__ void k_deg(const int* __restrict__ col, int e) {
    int i = blockIdx.x * blockDim.x + threadIdx.x;
    if (i < e) atomicAdd(&g_degi[col[i]], 1);
}

// scan1: block-local exclusive scan + fused dinv
__global__ void k_scan1() {
    __shared__ int sd[SCAN_BLK];
    int tx = threadIdx.x;
    int i = blockIdx.x * SCAN_BLK + tx;
    int v = (i < NN) ? g_degi[i] : 0;
    if (i < NN) g_dinv[i] = rsqrtf((float)(v + 1));
    sd[tx] = v;
    __syncthreads();
#pragma unroll
    for (int off = 1; off < SCAN_BLK; off <<= 1) {
        int t = (tx >= off) ? sd[tx - off] : 0;
        __syncthreads();
        sd[tx] += t;
        __syncthreads();
    }
    if (i < NN) g_start[i] = sd[tx] - v;
    if (tx == SCAN_BLK - 1) g_bsum[blockIdx.x] = sd[tx];
}

// scan3: each block scans the 98 partials in smem, adds offset, inits cursor
__global__ void k_scan3() {
    __shared__ int sb[128];
    int tx = threadIdx.x;
    if (tx < 128) sb[tx] = (tx < NBLK) ? g_bsum[tx] : 0;
    __syncthreads();
#pragma unroll
    for (int off = 1; off < 128; off <<= 1) {
        int t = 0;
        if (tx < 128 && tx >= off) t = sb[tx - off];
        __syncthreads();
        if (tx < 128) sb[tx] += t;
        __syncthreads();
    }
    int boff = (blockIdx.x == 0) ? 0 : sb[blockIdx.x - 1];
    int i = blockIdx.x * SCAN_BLK + tx;
    if (i < NN) {
        int s = g_start[i] + boff;
        g_start[i]  = s;
        g_cursor[i] = s;
    }
}

__global__ void k_sort(const int* __restrict__ row, const int* __restrict__ col, int e) {
    int i = blockIdx.x * blockDim.x + threadIdx.x;
    if (i < e) {
        int p = atomicAdd(&g_cursor[col[i]], 1);
        g_srow[p] = row[i];
    }
}

// ---------------------------------------------------------------------------
// bf16x3 GEMM via wmma. CTA 128x128, 8 warps (4x2), K chunks of 64.
// Writes UNSCALED y in fp16 (no dinv dependency).
#define A_LD   72
#define B_LD   136
#define AH_OFF 0
#define AL_OFF (128 * A_LD * 2)              // 18432
#define BH_OFF (AL_OFF + 128 * A_LD * 2)     // 36864
#define BL_OFF (BH_OFF + 64 * B_LD * 2)      // +17408
#define GEMM_SMEM (BL_OFF + 64 * B_LD * 2)   // 71680

__global__ void __launch_bounds__(256, 2)
k_gemm_mma(const float* __restrict__ A, int N) {
    extern __shared__ char sm[];
    __nv_bfloat16* As_h = (__nv_bfloat16*)(sm + AH_OFF);
    __nv_bfloat16* As_l = (__nv_bfloat16*)(sm + AL_OFF);
    __nv_bfloat16* Bs_h = (__nv_bfloat16*)(sm + BH_OFF);
    __nv_bfloat16* Bs_l = (__nv_bfloat16*)(sm + BL_OFF);

    const int tx = threadIdx.x;
    const int wid = tx >> 5;
    const int lane = tx & 31;
    const int wr = wid >> 1;
    const int wc = wid & 1;
    const int block_row = blockIdx.x * 128;

    wmma::fragment<wmma::accumulator, 16, 16, 16, float> acc[2][4];
#pragma unroll
    for (int i = 0; i < 2; i++)
#pragma unroll
        for (int j = 0; j < 4; j++) wmma::fill_fragment(acc[i][j], 0.0f);

    for (int kc = 0; kc < 4; kc++) {
        {
            uint32_t bh = s2u(Bs_h), bl = s2u(Bs_l);
#pragma unroll
            for (int it = 0; it < 4; it++) {
                int t = tx + 256 * it;
                int k = t >> 4, ng = t & 15;
                cpasync16(bh + (k * B_LD + ng * 8) * 2, g_Bhi + (size_t)(kc * 64 + k) * FOUT + ng * 8);
                cpasync16(bl + (k * B_LD + ng * 8) * 2, g_Blo + (size_t)(kc * 64 + k) * FOUT + ng * 8);
            }
            asm volatile("cp.async.commit_group;" ::: "memory");
        }
#pragma unroll
        for (int it = 0; it < 8; it++) {
            int t = tx + 256 * it;
            int r = t >> 4, cq = t & 15;
            int gr = block_row + r;
            float4 f = make_float4(0.f, 0.f, 0.f, 0.f);
            if (gr < N) f = *(const float4*)(A + (size_t)gr * FIN + kc * 64 + cq * 4);
            __nv_bfloat162 h0 = __float22bfloat162_rn(make_float2(f.x, f.y));
            __nv_bfloat162 h1 = __float22bfloat162_rn(make_float2(f.z, f.w));
            float2 hf0 = __bfloat1622float2(h0);
            float2 hf1 = __bfloat1622float2(h1);
            __nv_bfloat162 l0 = __float22bfloat162_rn(make_float2(f.x - hf0.x, f.y - hf0.y));
            __nv_bfloat162 l1 = __float22bfloat162_rn(make_float2(f.z - hf1.x, f.w - hf1.y));
            *(uint2*)(As_h + r * A_LD + cq * 4) = make_uint2(*(uint32_t*)&h0, *(uint32_t*)&h1);
            *(uint2*)(As_l + r * A_LD + cq * 4) = make_uint2(*(uint32_t*)&l0, *(uint32_t*)&l1);
        }
        asm volatile("cp.async.wait_group 0;" ::: "memory");
        __syncthreads();

#pragma unroll
        for (int kk = 0; kk < 4; kk++) {
            wmma::fragment<wmma::matrix_a, 16, 16, 16, __nv_bfloat16, wmma::row_major> ah[2], al[2];
#pragma unroll
            for (int i = 0; i < 2; i++) {
                const __nv_bfloat16* ap = As_h + (wr * 32 + i * 16) * A_LD + kk * 16;
                wmma::load_matrix_sync(ah[i], ap, A_LD);
                wmma::load_matrix_sync(al[i], ap + (AL_OFF - AH_OFF) / 2, A_LD);
            }
#pragma unroll
            for (int j = 0; j < 4; j++) {
                wmma::fragment<wmma::matrix_b, 16, 16, 16, __nv_bfloat16, wmma::row_major> bh, bl;
                const __nv_bfloat16* bp = Bs_h + (kk * 16) * B_LD + wc * 64 + j * 16;
                wmma::load_matrix_sync(bh, bp, B_LD);
                wmma::load_matrix_sync(bl, bp + (BL_OFF - BH_OFF) / 2, B_LD);
#pragma unroll
                for (int i = 0; i < 2; i++) {
                    wmma::mma_sync(acc[i][j], ah[i], bh, acc[i][j]);
                    wmma::mma_sync(acc[i][j], ah[i], bl, acc[i][j]);
                    wmma::mma_sync(acc[i][j], al[i], bh, acc[i][j]);
                }
            }
        }
        __syncthreads();
    }

    // Epilogue: stage fp32 (stride 68 -> conflict-free), convert to fp16 (unscaled)
    float* stage = (float*)sm + wid * 2176;
#pragma unroll
    for (int i = 0; i < 2; i++)
#pragma unroll
        for (int j = 0; j < 4; j++)
            wmma::store_matrix_sync(stage + i * 16 * 68 + j * 16, acc[i][j], 68, wmma::mem_row_major);
    __syncwarp();

    int grow = block_row + wr * 32 + lane;
    if (grow < N) {
        __half* yp = g_yh + (size_t)grow * FOUT + wc * 64;
        const float* sp = stage + lane * 68;
#pragma unroll
        for (int q = 0; q < 16; q++) {
            float4 v = *(const float4*)(sp + q * 4);
            __half2 p0 = __float22half2_rn(make_float2(v.x, v.y));
            __half2 p1 = __float22half2_rn(make_float2(v.z, v.w));
            *(uint2*)(yp + q * 4) = make_uint2(*(uint32_t*)&p0, *(uint32_t*)&p1);
        }
    }
}

// ---------------------------------------------------------------------------
// Gather-aggregate: acc = dinv[node]*y[node] + sum dinv[r]*y[r]; out = relu(dinv*acc+b)
static __device__ __forceinline__ float4 ldy4(const __half* base, int lane) {
    uint2 u = ((const uint2*)base)[lane];
    __half2 p0 = *(__half2*)&u.x;
    __half2 p1 = *(__half2*)&u.y;
    float2 f0 = __half22float2(p0);
    float2 f1 = __half22float2(p1);
    return make_float4(f0.x, f0.y, f1.x, f1.y);
}

__global__ void __launch_bounds__(256)
k_agg(const float* __restrict__ b, float* __restrict__ out, int N, int E, float ninv) {
    __shared__ float hpart[FOUT];
    __shared__ int is_last;
    const int tx = threadIdx.x;
    if (tx < FOUT) hpart[tx] = 0.0f;
    __syncthreads();

    const int lane = tx & 31;
    const int warp = tx >> 5;
    const int node = blockIdx.x * 8 + warp;

    float4 v = make_float4(0.f, 0.f, 0.f, 0.f);
    if (node < N) {
        float dvn = g_dinv[node];
        float4 sv = ldy4(g_yh + (size_t)node * FOUT, lane);
        float4 acc = make_float4(sv.x * dvn, sv.y * dvn, sv.z * dvn, sv.w * dvn);
        int s  = g_start[node];
        int e2 = (node + 1 < N) ? g_start[node + 1] : E;

        for (int base = s; base < e2; base += 32) {
            int cnt = min(32, e2 - base);
            int myidx = (lane < cnt) ? g_srow[base + lane] : 0;
            float mydv = (lane < cnt) ? g_dinv[myidx] : 0.0f;
            for (int j = 0; j < cnt; j++) {
                int r = __shfl_sync(0xffffffffu, myidx, j);
                float dvr = __shfl_sync(0xffffffffu, mydv, j);
                float4 vv = ldy4(g_yh + (size_t)r * FOUT, lane);
                acc.x = fmaf(vv.x, dvr, acc.x);
                acc.y = fmaf(vv.y, dvr, acc.y);
                acc.z = fmaf(vv.z, dvr, acc.z);
                acc.w = fmaf(vv.w, dvr, acc.w);
            }
        }

        float4 bv = ((const float4*)b)[lane];
        v.x = fmaxf(fmaf(acc.x, dvn, bv.x), 0.0f);
        v.y = fmaxf(fmaf(acc.y, dvn, bv.y), 0.0f);
        v.z = fmaxf(fmaf(acc.z, dvn, bv.z), 0.0f);
        v.w = fmaxf(fmaf(acc.w, dvn, bv.w), 0.0f);
        ((float4*)(out + (size_t)node * FOUT))[lane] = v;
    }

    atomicAdd(&hpart[lane * 4 + 0], v.x);
    atomicAdd(&hpart[lane * 4 + 1], v.y);
    atomicAdd(&hpart[lane * 4 + 2], v.z);
    atomicAdd(&hpart[lane * 4 + 3], v.w);
    __syncthreads();
    if (tx < FOUT) atomicAdd(&g_hsum[tx], hpart[tx]);

    if (tx == 0) {
        __threadfence();
        int t = atomicAdd(&g_ticket, 1);
        is_last = (t == (int)gridDim.x - 1) ? 1 : 0;
    }
    __syncthreads();
    if (is_last) {
        __threadfence();
        if (tx < FOUT) {
            float m = g_hsum[tx] * ninv;
            out[(size_t)N * FOUT + tx] = 1.0f / (1.0f + expf(-m));
        }
    }
}

// ---------------------------------------------------------------------------
extern "C" void kernel_launch(void* const* d_in, const int* in_sizes, int n_in,
                              void* d_out, int out_size) {
    const float* feat = (const float*)d_in[0];
    const int*   ei   = (const int*)d_in[1];
    const float* W    = (const float*)d_in[2];
    const float* b    = (const float*)d_in[3];
    float* out = (float*)d_out;

    int N = in_sizes[0] / FIN;
    int E = in_sizes[1] / 2;
    const int* rowp = ei;
    const int* colp = ei + E;

    static cudaStream_t s2 = nullptr;
    static cudaEvent_t evFork = nullptr, evJoin = nullptr;
    if (!s2) {
        cudaStreamCreateWithFlags(&s2, cudaStreamNonBlocking);
        cudaEventCreateWithFlags(&evFork, cudaEventDisableTiming);
        cudaEventCreateWithFlags(&evJoin, cudaEventDisableTiming);
        cudaFuncSetAttribute(k_gemm_mma, cudaFuncAttributeMaxDynamicSharedMemorySize, GEMM_SMEM);
    }

    // Fork: GEMM path on s2, prep chain on main stream, join before k_agg.
    cudaEventRecord(evFork, 0);
    cudaStreamWaitEvent(s2, evFork, 0);

    k_initW<<<(FIN * FOUT + 255) / 256, 256, 0, s2>>>(W);
    k_gemm_mma<<<(N + 127) / 128, 256, GEMM_SMEM, s2>>>(feat, N);
    cudaEventRecord(evJoin, s2);

    k_zero<<<392, 256>>>();
    k_deg<<<(E + 255) / 256, 256>>>(colp, E);
    k_scan1<<<NBLK, SCAN_BLK>>>();
    k_scan3<<<NBLK, SCAN_BLK>>>();
    k_sort<<<(E + 255) / 256, 256>>>(rowp, colp, E);

    cudaStreamWaitEvent(0, evJoin, 0);
    k_agg<<<(N + 7) / 8, 256>>>(b, out, N, E, 1.0f / (float)N);
}

// round 10
// speedup vs baseline: 1.3639x; 1.0076x over previous
#include <cuda_runtime.h>
#include <cuda_bf16.h>
#include <cuda_fp16.h>
#include <mma.h>
#include <math.h>
#include <cstdint>

using namespace nvcuda;

#define NN   100000
#define EE   1600000
#define FIN  256
#define FOUT 128
#define SCAN_BLK 1024
#define NBLK ((NN + SCAN_BLK - 1) / SCAN_BLK)   // 98

// Scratch (static __device__)
__device__ __half g_yh[(size_t)NN * FOUT];    // y = A@W (UNSCALED), fp16
__device__ int   g_degi[NN];
__device__ float g_dinv[NN];
__device__ int   g_start[NN];
__device__ int   g_cursor[NN];
__device__ int   g_srow[EE];
__device__ int   g_bsum[NBLK];
__device__ float g_hsum[FOUT];
__device__ int   g_ticket;
__device__ __nv_bfloat16 g_Bhi[FIN * FOUT];   // W split [k][n]
__device__ __nv_bfloat16 g_Blo[FIN * FOUT];

static __device__ __forceinline__ uint32_t s2u(const void* p) {
    return (uint32_t)__cvta_generic_to_shared(p);
}
static __device__ __forceinline__ void cpasync16(uint32_t dst, const void* src) {
    asm volatile("cp.async.cg.shared.global [%0], [%1], 16;"
                 :: "r"(dst), "l"(src) : "memory");
}

// ---------------------------------------------------------------------------
__global__ void k_zero() {
    int i = blockIdx.x * blockDim.x + threadIdx.x;
    int stride = gridDim.x * blockDim.x;
    for (int j = i; j < NN; j += stride) g_degi[j] = 0;
    if (i < FOUT) g_hsum[i] = 0.0f;
    if (i == 0)   g_ticket = 0;
}

__global__ void k_initW(const float* __restrict__ W) {
    int i = blockIdx.x * blockDim.x + threadIdx.x;
    if (i < FIN * FOUT) {
        float x = W[i];
        __nv_bfloat16 h = __float2bfloat16(x);
        g_Bhi[i] = h;
        g_Blo[i] = __float2bfloat16(x - __bfloat162float(h));
    }
}

// vectorized degree histogram: 4 edges per thread
__global__ void k_deg(const int* __restrict__ col, int e) {
    int i = blockIdx.x * blockDim.x + threadIdx.x;
    int base = i * 4;
    if (base + 4 <= e) {
        int4 c = *(const int4*)(col + base);
        atomicAdd(&g_degi[c.x], 1);
        atomicAdd(&g_degi[c.y], 1);
        atomicAdd(&g_degi[c.z], 1);
        atomicAdd(&g_degi[c.w], 1);
    } else {
        for (int j = base; j < e; j++) atomicAdd(&g_degi[col[j]], 1);
    }
}

// scan1: block-local exclusive scan + fused dinv
__global__ void k_scan1() {
    __shared__ int sd[SCAN_BLK];
    int tx = threadIdx.x;
    int i = blockIdx.x * SCAN_BLK + tx;
    int v = (i < NN) ? g_degi[i] : 0;
    if (i < NN) g_dinv[i] = rsqrtf((float)(v + 1));
    sd[tx] = v;
    __syncthreads();
#pragma unroll
    for (int off = 1; off < SCAN_BLK; off <<= 1) {
        int t = (tx >= off) ? sd[tx - off] : 0;
        __syncthreads();
        sd[tx] += t;
        __syncthreads();
    }
    if (i < NN) g_start[i] = sd[tx] - v;
    if (tx == SCAN_BLK - 1) g_bsum[blockIdx.x] = sd[tx];
}

// scan3: each block scans the 98 partials in smem, adds offset, inits cursor
__global__ void k_scan3() {
    __shared__ int sb[128];
    int tx = threadIdx.x;
    if (tx < 128) sb[tx] = (tx < NBLK) ? g_bsum[tx] : 0;
    __syncthreads();
#pragma unroll
    for (int off = 1; off < 128; off <<= 1) {
        int t = 0;
        if (tx < 128 && tx >= off) t = sb[tx - off];
        __syncthreads();
        if (tx < 128) sb[tx] += t;
        __syncthreads();
    }
    int boff = (blockIdx.x == 0) ? 0 : sb[blockIdx.x - 1];
    int i = blockIdx.x * SCAN_BLK + tx;
    if (i < NN) {
        int s = g_start[i] + boff;
        g_start[i]  = s;
        g_cursor[i] = s;
    }
}

__global__ void k_sort(const int* __restrict__ row, const int* __restrict__ col, int e) {
    int i = blockIdx.x * blockDim.x + threadIdx.x;
    if (i < e) {
        int p = atomicAdd(&g_cursor[col[i]], 1);
        g_srow[p] = row[i];
    }
}

// ---------------------------------------------------------------------------
// bf16x3 GEMM via wmma. CTA 128x128, 8 warps (4x2), K chunks of 64.
// Writes UNSCALED y in fp16.
#define A_LD   72
#define B_LD   136
#define AH_OFF 0
#define AL_OFF (128 * A_LD * 2)              // 18432
#define BH_OFF (AL_OFF + 128 * A_LD * 2)     // 36864
#define BL_OFF (BH_OFF + 64 * B_LD * 2)      // +17408
#define GEMM_SMEM (BL_OFF + 64 * B_LD * 2)   // 71680

__global__ void __launch_bounds__(256, 2)
k_gemm_mma(const float* __restrict__ A, int N) {
    extern __shared__ char sm[];
    __nv_bfloat16* As_h = (__nv_bfloat16*)(sm + AH_OFF);
    __nv_bfloat16* As_l = (__nv_bfloat16*)(sm + AL_OFF);
    __nv_bfloat16* Bs_h = (__nv_bfloat16*)(sm + BH_OFF);
    __nv_bfloat16* Bs_l = (__nv_bfloat16*)(sm + BL_OFF);

    const int tx = threadIdx.x;
    const int wid = tx >> 5;
    const int lane = tx & 31;
    const int wr = wid >> 1;
    const int wc = wid & 1;
    const int block_row = blockIdx.x * 128;

    wmma::fragment<wmma::accumulator, 16, 16, 16, float> acc[2][4];
#pragma unroll
    for (int i = 0; i < 2; i++)
#pragma unroll
        for (int j = 0; j < 4; j++) wmma::fill_fragment(acc[i][j], 0.0f);

    for (int kc = 0; kc < 4; kc++) {
        {
            uint32_t bh = s2u(Bs_h), bl = s2u(Bs_l);
#pragma unroll
            for (int it = 0; it < 4; it++) {
                int t = tx + 256 * it;
                int k = t >> 4, ng = t & 15;
                cpasync16(bh + (k * B_LD + ng * 8) * 2, g_Bhi + (size_t)(kc * 64 + k) * FOUT + ng * 8);
                cpasync16(bl + (k * B_LD + ng * 8) * 2, g_Blo + (size_t)(kc * 64 + k) * FOUT + ng * 8);
            }
            asm volatile("cp.async.commit_group;" ::: "memory");
        }
#pragma unroll
        for (int it = 0; it < 8; it++) {
            int t = tx + 256 * it;
            int r = t >> 4, cq = t & 15;
            int gr = block_row + r;
            float4 f = make_float4(0.f, 0.f, 0.f, 0.f);
            if (gr < N) f = *(const float4*)(A + (size_t)gr * FIN + kc * 64 + cq * 4);
            __nv_bfloat162 h0 = __float22bfloat162_rn(make_float2(f.x, f.y));
            __nv_bfloat162 h1 = __float22bfloat162_rn(make_float2(f.z, f.w));
            float2 hf0 = __bfloat1622float2(h0);
            float2 hf1 = __bfloat1622float2(h1);
            __nv_bfloat162 l0 = __float22bfloat162_rn(make_float2(f.x - hf0.x, f.y - hf0.y));
            __nv_bfloat162 l1 = __float22bfloat162_rn(make_float2(f.z - hf1.x, f.w - hf1.y));
            *(uint2*)(As_h + r * A_LD + cq * 4) = make_uint2(*(uint32_t*)&h0, *(uint32_t*)&h1);
            *(uint2*)(As_l + r * A_LD + cq * 4) = make_uint2(*(uint32_t*)&l0, *(uint32_t*)&l1);
        }
        asm volatile("cp.async.wait_group 0;" ::: "memory");
        __syncthreads();

#pragma unroll
        for (int kk = 0; kk < 4; kk++) {
            wmma::fragment<wmma::matrix_a, 16, 16, 16, __nv_bfloat16, wmma::row_major> ah[2], al[2];
#pragma unroll
            for (int i = 0; i < 2; i++) {
                const __nv_bfloat16* ap = As_h + (wr * 32 + i * 16) * A_LD + kk * 16;
                wmma::load_matrix_sync(ah[i], ap, A_LD);
                wmma::load_matrix_sync(al[i], ap + (AL_OFF - AH_OFF) / 2, A_LD);
            }
#pragma unroll
            for (int j = 0; j < 4; j++) {
                wmma::fragment<wmma::matrix_b, 16, 16, 16, __nv_bfloat16, wmma::row_major> bh, bl;
                const __nv_bfloat16* bp = Bs_h + (kk * 16) * B_LD + wc * 64 + j * 16;
                wmma::load_matrix_sync(bh, bp, B_LD);
                wmma::load_matrix_sync(bl, bp + (BL_OFF - BH_OFF) / 2, B_LD);
#pragma unroll
                for (int i = 0; i < 2; i++) {
                    wmma::mma_sync(acc[i][j], ah[i], bh, acc[i][j]);
                    wmma::mma_sync(acc[i][j], ah[i], bl, acc[i][j]);
                    wmma::mma_sync(acc[i][j], al[i], bh, acc[i][j]);
                }
            }
        }
        __syncthreads();
    }

    float* stage = (float*)sm + wid * 2176;
#pragma unroll
    for (int i = 0; i < 2; i++)
#pragma unroll
        for (int j = 0; j < 4; j++)
            wmma::store_matrix_sync(stage + i * 16 * 68 + j * 16, acc[i][j], 68, wmma::mem_row_major);
    __syncwarp();

    int grow = block_row + wr * 32 + lane;
    if (grow < N) {
        __half* yp = g_yh + (size_t)grow * FOUT + wc * 64;
        const float* sp = stage + lane * 68;
#pragma unroll
        for (int q = 0; q < 16; q++) {
            float4 v = *(const float4*)(sp + q * 4);
            __half2 p0 = __float22half2_rn(make_float2(v.x, v.y));
            __half2 p1 = __float22half2_rn(make_float2(v.z, v.w));
            *(uint2*)(yp + q * 4) = make_uint2(*(uint32_t*)&p0, *(uint32_t*)&p1);
        }
    }
}

// ---------------------------------------------------------------------------
// Gather-aggregate with per-edge dinv, 4-edge unroll (MLP=4).
static __device__ __forceinline__ float4 ldy4(const __half* base, int lane) {
    uint2 u = ((const uint2*)base)[lane];
    __half2 p0 = *(__half2*)&u.x;
    __half2 p1 = *(__half2*)&u.y;
    float2 f0 = __half22float2(p0);
    float2 f1 = __half22float2(p1);
    return make_float4(f0.x, f0.y, f1.x, f1.y);
}

__global__ void __launch_bounds__(256)
k_agg(const float* __restrict__ b, float* __restrict__ out, int N, int E, float ninv) {
    __shared__ float hpart[FOUT];
    __shared__ int is_last;
    const int tx = threadIdx.x;
    if (tx < FOUT) hpart[tx] = 0.0f;
    __syncthreads();

    const int lane = tx & 31;
    const int warp = tx >> 5;
    const int node = blockIdx.x * 8 + warp;

    float4 v = make_float4(0.f, 0.f, 0.f, 0.f);
    if (node < N) {
        float dvn = g_dinv[node];
        float4 sv = ldy4(g_yh + (size_t)node * FOUT, lane);
        float4 acc = make_float4(sv.x * dvn, sv.y * dvn, sv.z * dvn, sv.w * dvn);
        int s  = g_start[node];
        int e2 = (node + 1 < N) ? g_start[node + 1] : E;

        for (int base = s; base < e2; base += 32) {
            int cnt = min(32, e2 - base);
            int myidx = (lane < cnt) ? g_srow[base + lane] : 0;
            float mydv = (lane < cnt) ? g_dinv[myidx] : 0.0f;
            int j = 0;
            for (; j + 4 <= cnt; j += 4) {
                int r0 = __shfl_sync(0xffffffffu, myidx, j + 0);
                int r1 = __shfl_sync(0xffffffffu, myidx, j + 1);
                int r2 = __shfl_sync(0xffffffffu, myidx, j + 2);
                int r3 = __shfl_sync(0xffffffffu, myidx, j + 3);
                float d0 = __shfl_sync(0xffffffffu, mydv, j + 0);
                float d1 = __shfl_sync(0xffffffffu, mydv, j + 1);
                float d2 = __shfl_sync(0xffffffffu, mydv, j + 2);
                float d3 = __shfl_sync(0xffffffffu, mydv, j + 3);
                float4 v0 = ldy4(g_yh + (size_t)r0 * FOUT, lane);
                float4 v1 = ldy4(g_yh + (size_t)r1 * FOUT, lane);
                float4 v2 = ldy4(g_yh + (size_t)r2 * FOUT, lane);
                float4 v3 = ldy4(g_yh + (size_t)r3 * FOUT, lane);
                acc.x = fmaf(v0.x, d0, acc.x); acc.y = fmaf(v0.y, d0, acc.y);
                acc.z = fmaf(v0.z, d0, acc.z); acc.w = fmaf(v0.w, d0, acc.w);
                acc.x = fmaf(v1.x, d1, acc.x); acc.y = fmaf(v1.y, d1, acc.y);
                acc.z = fmaf(v1.z, d1, acc.z); acc.w = fmaf(v1.w, d1, acc.w);
                acc.x = fmaf(v2.x, d2, acc.x); acc.y = fmaf(v2.y, d2, acc.y);
                acc.z = fmaf(v2.z, d2, acc.z); acc.w = fmaf(v2.w, d2, acc.w);
                acc.x = fmaf(v3.x, d3, acc.x); acc.y = fmaf(v3.y, d3, acc.y);
                acc.z = fmaf(v3.z, d3, acc.z); acc.w = fmaf(v3.w, d3, acc.w);
            }
            for (; j < cnt; j++) {
                int r = __shfl_sync(0xffffffffu, myidx, j);
                float dvr = __shfl_sync(0xffffffffu, mydv, j);
                float4 vv = ldy4(g_yh + (size_t)r * FOUT, lane);
                acc.x = fmaf(vv.x, dvr, acc.x);
                acc.y = fmaf(vv.y, dvr, acc.y);
                acc.z = fmaf(vv.z, dvr, acc.z);
                acc.w = fmaf(vv.w, dvr, acc.w);
            }
        }

        float4 bv = ((const float4*)b)[lane];
        v.x = fmaxf(fmaf(acc.x, dvn, bv.x), 0.0f);
        v.y = fmaxf(fmaf(acc.y, dvn, bv.y), 0.0f);
        v.z = fmaxf(fmaf(acc.z, dvn, bv.z), 0.0f);
        v.w = fmaxf(fmaf(acc.w, dvn, bv.w), 0.0f);
        ((float4*)(out + (size_t)node * FOUT))[lane] = v;
    }

    atomicAdd(&hpart[lane * 4 + 0], v.x);
    atomicAdd(&hpart[lane * 4 + 1], v.y);
    atomicAdd(&hpart[lane * 4 + 2], v.z);
    atomicAdd(&hpart[lane * 4 + 3], v.w);
    __syncthreads();
    if (tx < FOUT) atomicAdd(&g_hsum[tx], hpart[tx]);

    if (tx == 0) {
        __threadfence();
        int t = atomicAdd(&g_ticket, 1);
        is_last = (t == (int)gridDim.x - 1) ? 1 : 0;
    }
    __syncthreads();
    if (is_last) {
        __threadfence();
        if (tx < FOUT) {
            float m = g_hsum[tx] * ninv;
            out[(size_t)N * FOUT + tx] = 1.0f / (1.0f + expf(-m));
        }
    }
}

// ---------------------------------------------------------------------------
extern "C" void kernel_launch(void* const* d_in, const int* in_sizes, int n_in,
                              void* d_out, int out_size) {
    const float* feat = (const float*)d_in[0];
    const int*   ei   = (const int*)d_in[1];
    const float* W    = (const float*)d_in[2];
    const float* b    = (const float*)d_in[3];
    float* out = (float*)d_out;

    int N = in_sizes[0] / FIN;
    int E = in_sizes[1] / 2;
    const int* rowp = ei;
    const int* colp = ei + E;

    static cudaStream_t s2 = nullptr;
    static cudaEvent_t evFork = nullptr, evJoin = nullptr;
    if (!s2) {
        cudaStreamCreateWithFlags(&s2, cudaStreamNonBlocking);
        cudaEventCreateWithFlags(&evFork, cudaEventDisableTiming);
        cudaEventCreateWithFlags(&evJoin, cudaEventDisableTiming);
        cudaFuncSetAttribute(k_gemm_mma, cudaFuncAttributeMaxDynamicSharedMemorySize, GEMM_SMEM);
    }

    cudaEventRecord(evFork, 0);
    cudaStreamWaitEvent(s2, evFork, 0);

    k_initW<<<(FIN * FOUT + 255) / 256, 256, 0, s2>>>(W);
    k_gemm_mma<<<(N + 127) / 128, 256, GEMM_SMEM, s2>>>(feat, N);
    cudaEventRecord(evJoin, s2);

    k_zero<<<392, 256>>>();
    k_deg<<<(E / 4 + 255) / 256, 256>>>(colp, E);
    k_scan1<<<NBLK, SCAN_BLK>>>();
    k_scan3<<<NBLK, SCAN_BLK>>>();
    k_sort<<<(E + 255) / 256, 256>>>(rowp, colp, E);

    cudaStreamWaitEvent(0, evJoin, 0);
    k_agg<<<(N + 7) / 8, 256>>>(b, out, N, E, 1.0f / (float)N);
}